// round 3
// baseline (speedup 1.0000x reference)
#include <cuda_runtime.h>
#include <math_constants.h>

// BackupBarrierCBF: 50-step braking rollout of ego+agent unicycles, then
// min-over-time oriented-box separation distance, squashed by 5*tanh(h/10).
//
// R3: latency-bound fix (occ 18%, no pipe saturated):
//  - ILP-2: each thread rolls out TWO independent elements, chains interleaved
//  - one MUFU.RCP shared across the 4 tanh denominators (exp-arg clamped at 20
//    so the product of (1+e) terms cannot overflow); redistribution via FMULs
//    on the underused fma pipe
//  - 1-warp blocks for near-perfect per-SM wave balance

#define N_T 50

__global__ __launch_bounds__(32)
void cbf_kernel(const float* __restrict__ data, float* __restrict__ out,
                int n, int half)
{
    int i = blockIdx.x * blockDim.x + threadIdx.x;
    if (i >= half) return;
    int j = i + half;
    bool has2 = (j < n);

    const float* p0 = data + (size_t)i * 15;
    const float* p1 = data + (size_t)(has2 ? j : i) * 15;

    // ---- element 0 ----
    float xe0 = p0[0], ye0 = p0[1], ve0 = p0[2], the0 = p0[3];
    float xa0 = p0[4], ya0 = p0[5], va0 = p0[6], tha0 = p0[7];
    float ee00 = p0[8], ee10 = p0[9], ae00 = p0[11], ae10 = p0[12];
    float dt0 = p0[14];
    // ---- element 1 ----
    float xe1 = p1[0], ye1 = p1[1], ve1 = p1[2], the1 = p1[3];
    float xa1 = p1[4], ya1 = p1[5], va1 = p1[6], tha1 = p1[7];
    float ee01 = p1[8], ee11 = p1[9], ae01 = p1[11], ae11 = p1[12];
    float dt1 = p1[14];

    // dynamics heading (slot 3) constant (turn control == 0): hoist
    float se0, ce0, sa0, ca0, se1, ce1, sa1, ca1;
    __sincosf(the0, &se0, &ce0);
    __sincosf(tha0, &sa0, &ca0);
    __sincosf(the1, &se1, &ce1);
    __sincosf(tha1, &sa1, &ca1);
    float dtce0 = dt0 * ce0, dtse0 = dt0 * se0;
    float dtca0 = dt0 * ca0, dtsa0 = dt0 * sa0;
    float dtce1 = dt1 * ce1, dtse1 = dt1 * se1;
    float dtca1 = dt1 * ca1, dtsa1 = dt1 * sa1;
    float m9dt0 = -9.0f * dt0, m9dt1 = -9.0f * dt1;

    float rag0 = 0.5f * sqrtf(ae00 * ae00 + ae10 * ae10);
    float reg0 = 0.5f * sqrtf(ee00 * ee00 + ee10 * ee10);
    float t1x0 = 0.5f * ee00 + rag0, t1y0 = 0.5f * ee10 + rag0;
    float t2x0 = 0.5f * ae00 + reg0, t2y0 = 0.5f * ae10 + reg0;
    float rag1 = 0.5f * sqrtf(ae01 * ae01 + ae11 * ae11);
    float reg1 = 0.5f * sqrtf(ee01 * ee01 + ee11 * ee11);
    float t1x1 = 0.5f * ee01 + rag1, t1y1 = 0.5f * ee11 + rag1;
    float t2x1 = 0.5f * ae01 + reg1, t2y1 = 0.5f * ae11 + reg1;

    float hmin0 = CUDART_INF_F, hmin1 = CUDART_INF_F;

#pragma unroll 2
    for (int t = 0; t < N_T; t++) {
        // --- controller: tanh(2v) = (1-e)/(1+e), e = exp(min(-4v, 20)) ---
        // (clamp keeps the 4-way product below FLT_MAX; tanh err from clamp ~4e-9)
        float Ee0 = __expf(fminf(-4.0f * ve0, 20.0f));
        float Ea0 = __expf(fminf(-4.0f * va0, 20.0f));
        float Ee1 = __expf(fminf(-4.0f * ve1, 20.0f));
        float Ea1 = __expf(fminf(-4.0f * va1, 20.0f));

        float de0 = 1.0f + Ee0, da0 = 1.0f + Ea0;
        float de1 = 1.0f + Ee1, da1 = 1.0f + Ea1;
        float q0 = de0 * da0, q1 = de1 * da1;
        float r  = __fdividef(1.0f, q0 * q1);     // single MUFU.RCP for 4 denoms
        float r0 = r * q1, r1 = r * q0;
        float ie0 = r0 * da0, ia0 = r0 * de0;
        float ie1 = r1 * da1, ia1 = r1 * de1;

        float te0 = (1.0f - Ee0) * ie0, ta0 = (1.0f - Ea0) * ia0;
        float te1 = (1.0f - Ee1) * ie1, ta1 = (1.0f - Ea1) * ia1;

        // --- Euler step (positions use pre-step v) ---
        xe0 = fmaf(dtce0, ve0, xe0);  ye0 = fmaf(dtse0, ve0, ye0);
        xa0 = fmaf(dtca0, va0, xa0);  ya0 = fmaf(dtsa0, va0, ya0);
        xe1 = fmaf(dtce1, ve1, xe1);  ye1 = fmaf(dtse1, ve1, ye1);
        xa1 = fmaf(dtca1, va1, xa1);  ya1 = fmaf(dtsa1, va1, ya1);
        ve0 = fmaf(m9dt0, te0, ve0);  va0 = fmaf(m9dt0, ta0, va0);
        ve1 = fmaf(m9dt1, te1, ve1);  va1 = fmaf(m9dt1, ta1, va1);

        // --- oriented-box separation at post-step state ---
        // rotation angle = post-step VELOCITY (reference passes [x,y,v] as pose)
        float sve0, cve0, sva0, cva0, sve1, cve1, sva1, cva1;
        __sincosf(ve0, &sve0, &cve0);
        __sincosf(va0, &sva0, &cva0);
        __sincosf(ve1, &sve1, &cve1);
        __sincosf(va1, &sva1, &cva1);

        float dx0 = xa0 - xe0, dy0 = ya0 - ye0;
        float r1x0 = fabsf(fmaf(cve0, dx0,  sve0 * dy0)) - t1x0;
        float r1y0 = fabsf(fmaf(cve0, dy0, -sve0 * dx0)) - t1y0;
        float r2x0 = fabsf(fmaf(cva0, dx0,  sva0 * dy0)) - t2x0;
        float r2y0 = fabsf(fmaf(sva0, dx0, -cva0 * dy0)) - t2y0;
        float d0 = fmaxf(fmaxf(r1x0, r1y0), fmaxf(r2x0, r2y0));
        hmin0 = fminf(hmin0, d0);

        float dx1 = xa1 - xe1, dy1 = ya1 - ye1;
        float r1x1 = fabsf(fmaf(cve1, dx1,  sve1 * dy1)) - t1x1;
        float r1y1 = fabsf(fmaf(cve1, dy1, -sve1 * dx1)) - t1y1;
        float r2x1 = fabsf(fmaf(cva1, dx1,  sva1 * dy1)) - t2x1;
        float r2y1 = fabsf(fmaf(sva1, dx1, -cva1 * dy1)) - t2y1;
        float d1 = fmaxf(fmaxf(r1x1, r1y1), fmaxf(r2x1, r2y1));
        hmin1 = fminf(hmin1, d1);
    }

    // (sigmoid(h/5) - 0.5) * 2 * 5 == 5 * tanh(h/10)
    out[i] = 5.0f * tanhf(hmin0 * 0.1f);
    if (has2) out[j] = 5.0f * tanhf(hmin1 * 0.1f);
}

extern "C" void kernel_launch(void* const* d_in, const int* in_sizes, int n_in,
                              void* d_out, int out_size)
{
    const float* data = (const float*)d_in[0];
    float* out = (float*)d_out;
    int n = out_size;                 // B*A elements
    int half = (n + 1) / 2;
    int threads = 32;                 // 1 warp per block -> even SM balance
    int blocks = (half + threads - 1) / threads;
    cbf_kernel<<<blocks, threads>>>(data, out, n, half);
}

// round 4
// speedup vs baseline: 1.1775x; 1.1775x over previous
#include <cuda_runtime.h>
#include <math_constants.h>

// BackupBarrierCBF: 50-step braking rollout of ego+agent unicycles, then
// min-over-time oriented-box separation distance, squashed by 5*tanh(h/10).
//
// R4: TLP fix. R3 showed ILP-2 loses (occ 9.9%). Instead split each element
// across TWO lanes (even=ego, odd=agent): 4096 warps (2x R2), each thread
// runs one vehicle (1 exp + 1 rcp + 1 sincos per iter). The pair exchanges
// position and half-max via 3 shfl.bfly per iter — off the loop-carried
// (v -> tanh -> v) critical path. Fully symmetric, no divergence.

#define N_T 50

__global__ __launch_bounds__(64)
void cbf_kernel(const float* __restrict__ data, float* __restrict__ out,
                int n, int n2)
{
    int g = blockIdx.x * blockDim.x + threadIdx.x;
    bool active = (g < n2);
    int side = g & 1;                      // 0 = ego, 1 = agent
    int e = g >> 1;
    if (e >= n) e = n - 1;                 // keep pairs lane-consistent in tail

    const float* p = data + (size_t)e * 15;
    int sb = side * 4;
    float x  = p[sb + 0], y = p[sb + 1], v = p[sb + 2], th = p[sb + 3];
    int eo = 8 + side * 3;                 // own extent (ego:8,9  agent:11,12)
    int oo = 11 - side * 3;                // other vehicle's extent
    float ex0 = p[eo], ex1 = p[eo + 1];
    float ox0 = p[oo], ox1 = p[oo + 1];
    float dt  = p[14];

    // dynamics heading (slot 3) constant (turn control == 0): hoist
    float s, c;
    __sincosf(th, &s, &c);
    float dtc = dt * c, dts = dt * s;
    float m9dt = -9.0f * dt;               // v += dt * (-9 * tanh(2v))

    // dis_own = |R(-v_own)*(p_partner - p_own)| - 0.5*ext_own - r_other
    float r_other = 0.5f * sqrtf(ox0 * ox0 + ox1 * ox1);
    float tx = 0.5f * ex0 + r_other, ty = 0.5f * ex1 + r_other;

    float hmin = CUDART_INF_F;

#pragma unroll 2
    for (int t = 0; t < N_T; t++) {
        // controller + Euler step (u and dxdt from pre-step state)
        // tanh(2v) = (1 - e)/(1 + e), e = exp(-4v)   (accurate: feeds recursion)
        float E  = __expf(-4.0f * v);
        float tn = (1.0f - E) * __fdividef(1.0f, 1.0f + E);
        x = fmaf(dtc, v, x);
        y = fmaf(dts, v, y);
        v = fmaf(m9dt, tn, v);

        // oriented-box separation at post-step state
        // rotation angle = post-step VELOCITY (reference passes [x,y,v] as pose)
        float sv, cv;
        __sincosf(v, &sv, &cv);

        float px = __shfl_xor_sync(0xFFFFFFFFu, x, 1);
        float py = __shfl_xor_sync(0xFFFFFFFFu, y, 1);
        float dx = px - x, dy = py - y;

        // rel = R(-v)*d : relx = cv*dx + sv*dy ; rely = -sv*dx + cv*dy
        float rx = fabsf(fmaf(cv, dx,  sv * dy)) - tx;
        float ry = fabsf(fmaf(cv, dy, -sv * dx)) - ty;
        float m  = fmaxf(rx, ry);

        float pm = __shfl_xor_sync(0xFFFFFFFFu, m, 1);
        hmin = fminf(hmin, fmaxf(m, pm));
    }

    // (sigmoid(h/5) - 0.5) * 2 * 5 == 5 * tanh(h/10) ; accurate path, runs once
    if (active && side == 0)
        out[e] = 5.0f * tanhf(hmin * 0.1f);
}

extern "C" void kernel_launch(void* const* d_in, const int* in_sizes, int n_in,
                              void* d_out, int out_size)
{
    const float* data = (const float*)d_in[0];
    float* out = (float*)d_out;
    int n  = out_size;        // B*A elements
    int n2 = 2 * n;           // one thread per vehicle
    int threads = 64;
    int blocks = (n2 + threads - 1) / threads;
    cbf_kernel<<<blocks, threads>>>(data, out, n, n2);
}

// round 5
// speedup vs baseline: 1.4060x; 1.1940x over previous
#include <cuda_runtime.h>
#include <math_constants.h>

// BackupBarrierCBF: 50-step braking rollout of ego+agent unicycles, then
// min-over-time oriented-box separation distance, squashed by 5*tanh(h/10).
//
// R5: issue-bound fix. R4 (vehicle-split, occ 32%, issue 66%) showed more TLP
// stopped paying; cut instructions instead:
//  - controller tanh via HW tanh.approx.f32 (1 MUFU; saturates exactly for
//    |arg|>8 where most of the braking happens) -> 6 instrs -> 2, MUFU 4->3,
//    loop-carried v-chain 52 -> 24 cycles
//  - unroll 5 to amortize loop overhead
//  - final output squash stays accurate tanhf (single eval, error-critical)

#define N_T 50

__device__ __forceinline__ float htanh(float x) {
    float r;
    asm("tanh.approx.f32 %0, %1;" : "=f"(r) : "f"(x));
    return r;
}

__global__ __launch_bounds__(64)
void cbf_kernel(const float* __restrict__ data, float* __restrict__ out,
                int n, int n2)
{
    int g = blockIdx.x * blockDim.x + threadIdx.x;
    bool active = (g < n2);
    int side = g & 1;                      // 0 = ego, 1 = agent
    int e = g >> 1;
    if (e >= n) e = n - 1;                 // keep pairs lane-consistent in tail

    const float* p = data + (size_t)e * 15;
    int sb = side * 4;
    float x  = p[sb + 0], y = p[sb + 1], v = p[sb + 2], th = p[sb + 3];
    int eo = 8 + side * 3;                 // own extent (ego:8,9  agent:11,12)
    int oo = 11 - side * 3;                // other vehicle's extent
    float ex0 = p[eo], ex1 = p[eo + 1];
    float ox0 = p[oo], ox1 = p[oo + 1];
    float dt  = p[14];

    // dynamics heading (slot 3) constant (turn control == 0): hoist
    float s, c;
    __sincosf(th, &s, &c);
    float dtc = dt * c, dts = dt * s;
    float m9dt = -9.0f * dt;               // v += dt * (-9 * tanh(2v))

    // dis_own = |R(-v_own)*(p_partner - p_own)| - 0.5*ext_own - r_other
    float r_other = 0.5f * sqrtf(ox0 * ox0 + ox1 * ox1);
    float tx = 0.5f * ex0 + r_other, ty = 0.5f * ex1 + r_other;

    float hmin = CUDART_INF_F;

#pragma unroll 5
    for (int t = 0; t < N_T; t++) {
        // controller + Euler step (u and dxdt from pre-step state)
        float tn = htanh(2.0f * v);        // HW tanh: exact saturation |arg|>~8
        x = fmaf(dtc, v, x);
        y = fmaf(dts, v, y);
        v = fmaf(m9dt, tn, v);

        // oriented-box separation at post-step state
        // rotation angle = post-step VELOCITY (reference passes [x,y,v] as pose)
        float sv, cv;
        __sincosf(v, &sv, &cv);

        float px = __shfl_xor_sync(0xFFFFFFFFu, x, 1);
        float py = __shfl_xor_sync(0xFFFFFFFFu, y, 1);
        float dx = px - x, dy = py - y;

        // rel = R(-v)*d : relx = cv*dx + sv*dy ; rely = -sv*dx + cv*dy
        float rx = fabsf(fmaf(cv, dx,  sv * dy)) - tx;
        float ry = fabsf(fmaf(cv, dy, -sv * dx)) - ty;
        float m  = fmaxf(rx, ry);

        float pm = __shfl_xor_sync(0xFFFFFFFFu, m, 1);
        hmin = fminf(hmin, fmaxf(m, pm));
    }

    // (sigmoid(h/5) - 0.5) * 2 * 5 == 5 * tanh(h/10) ; accurate path, runs once
    if (active && side == 0)
        out[e] = 5.0f * tanhf(hmin * 0.1f);
}

extern "C" void kernel_launch(void* const* d_in, const int* in_sizes, int n_in,
                              void* d_out, int out_size)
{
    const float* data = (const float*)d_in[0];
    float* out = (float*)d_out;
    int n  = out_size;        // B*A elements
    int n2 = 2 * n;           // one thread per vehicle
    int threads = 64;
    int blocks = (n2 + threads - 1) / threads;
    cbf_kernel<<<blocks, threads>>>(data, out, n, n2);
}